// round 7
// baseline (speedup 1.0000x reference)
#include <cuda_runtime.h>
#include <math.h>

#define NN 10000
#define NV 2500            // NN/4
#define OUTF 64
#define SMAX 10016
#define NSORT 10048        // padded sorted-list length
#define NBUCK 16384

// ---- static scratch ----
__device__ float    g_Wh[NN * OUTF];
__device__ float    g_esrc[NN];
__device__ float    g_ed[NN];
__device__ int      g_Emax;
__device__ float2   g_pb2[NN];        // {bp=exp(ed-E), bn=exp(0.2(ed-E))}
__device__ float    g_hT[NN];         // hub*0.01
__device__ unsigned g_nib4[(size_t)(NN / 4) * NV];
__device__ float2   g_rw[NN];         // {py=1/S', pz=rho/S'}
__device__ int      g_sj[(size_t)NN * SMAX];
// sort machinery
__device__ float    g_u[NN];          // u_adj (slacked, clamped >=0)
__device__ float2   g_vu[NN];         // {v_adj, u_adj}
__device__ int      g_histU[NBUCK], g_histV[NBUCK];
__device__ int      g_offU[NBUCK + 1], g_offV[NBUCK + 1];
__device__ int      g_curU[NBUCK], g_curV[NBUCK];
__device__ float    g_sortU[NSORT];
__device__ int      g_idxU[NSORT];
__device__ float2   g_sortV[NSORT];
__device__ int      g_idxV[NSORT];

__device__ __forceinline__ int fkey(float x) {
    int ix = __float_as_int(x);
    return ix >= 0 ? ix : (ix ^ 0x7fffffff);
}
__device__ __forceinline__ float funkey(int k) {
    return __int_as_float(k >= 0 ? k : (k ^ 0x7fffffff));
}
__device__ __forceinline__ unsigned buck(float x) {   // x >= 0 (or NaN/inf)
    unsigned b = __float_as_uint(x) >> 17;
    return b > (NBUCK - 1u) ? (NBUCK - 1u) : b;
}

// ---------------------------------------------------------------------------
// K0: zero histograms + pad sorted arrays
// ---------------------------------------------------------------------------
__global__ void k_pad() {
    int i = blockIdx.x * 256 + threadIdx.x;
    if (i < NBUCK) { g_histU[i] = 0; g_histV[i] = 0; }
    if (i >= NN && i < NSORT) {
        float inf = __int_as_float(0x7F800000);
        g_sortU[i] = inf;
        float2 f; f.x = inf; f.y = inf;
        g_sortV[i] = f;
        g_idxU[i] = 0; g_idxV[i] = 0;
    }
}

// ---------------------------------------------------------------------------
// K1: Wh = h @ W (64x64 tile) + fused edge dots + Emax
// ---------------------------------------------------------------------------
__global__ void k_gemm(const float* __restrict__ h, const float* __restrict__ W,
                       const float* __restrict__ a_src, const float* __restrict__ a_dst) {
    __shared__ float h_s[64][33];
    __shared__ float W_s[32][64];
    __shared__ int bmax;
    int tid = threadIdx.x;
    if (tid == 0) bmax = 0x80000000;
    int tx = tid & 15, ty = tid >> 4;
    int gr0 = blockIdx.x * 64;
    float acc[4][4];
#pragma unroll
    for (int i = 0; i < 4; i++)
#pragma unroll
        for (int j = 0; j < 4; j++) acc[i][j] = 0.f;

    for (int k0 = 0; k0 < 512; k0 += 32) {
        __syncthreads();
#pragma unroll
        for (int it = 0; it < 2; it++) {
            int idx = it * 256 + tid;
            int row = idx >> 3, q = idx & 7;
            float4 h4 = make_float4(0.f, 0.f, 0.f, 0.f);
            if (gr0 + row < NN)
                h4 = *reinterpret_cast<const float4*>(h + (size_t)(gr0 + row) * 512 + k0 + q * 4);
            h_s[row][q * 4 + 0] = h4.x; h_s[row][q * 4 + 1] = h4.y;
            h_s[row][q * 4 + 2] = h4.z; h_s[row][q * 4 + 3] = h4.w;
        }
#pragma unroll
        for (int it = 0; it < 2; it++) {
            int idx = it * 256 + tid;
            int kk = idx >> 4, c4 = (idx & 15) * 4;
            float4 w4 = *reinterpret_cast<const float4*>(W + (size_t)(k0 + kk) * OUTF + c4);
            *reinterpret_cast<float4*>(&W_s[kk][c4]) = w4;
        }
        __syncthreads();
#pragma unroll
        for (int kk = 0; kk < 32; kk++) {
            float4 wv = *reinterpret_cast<const float4*>(&W_s[kk][tx * 4]);
            float hv0 = h_s[ty * 4 + 0][kk];
            float hv1 = h_s[ty * 4 + 1][kk];
            float hv2 = h_s[ty * 4 + 2][kk];
            float hv3 = h_s[ty * 4 + 3][kk];
            acc[0][0] = fmaf(hv0, wv.x, acc[0][0]); acc[0][1] = fmaf(hv0, wv.y, acc[0][1]);
            acc[0][2] = fmaf(hv0, wv.z, acc[0][2]); acc[0][3] = fmaf(hv0, wv.w, acc[0][3]);
            acc[1][0] = fmaf(hv1, wv.x, acc[1][0]); acc[1][1] = fmaf(hv1, wv.y, acc[1][1]);
            acc[1][2] = fmaf(hv1, wv.z, acc[1][2]); acc[1][3] = fmaf(hv1, wv.w, acc[1][3]);
            acc[2][0] = fmaf(hv2, wv.x, acc[2][0]); acc[2][1] = fmaf(hv2, wv.y, acc[2][1]);
            acc[2][2] = fmaf(hv2, wv.z, acc[2][2]); acc[2][3] = fmaf(hv2, wv.w, acc[2][3]);
            acc[3][0] = fmaf(hv3, wv.x, acc[3][0]); acc[3][1] = fmaf(hv3, wv.y, acc[3][1]);
            acc[3][2] = fmaf(hv3, wv.z, acc[3][2]); acc[3][3] = fmaf(hv3, wv.w, acc[3][3]);
        }
    }
    float4 as4 = *reinterpret_cast<const float4*>(a_src + tx * 4);
    float4 ad4 = *reinterpret_cast<const float4*>(a_dst + tx * 4);
#pragma unroll
    for (int i = 0; i < 4; i++) {
        int row = gr0 + ty * 4 + i;
        if (row < NN) {
            float4 o; o.x = acc[i][0]; o.y = acc[i][1]; o.z = acc[i][2]; o.w = acc[i][3];
            *reinterpret_cast<float4*>(g_Wh + (size_t)row * OUTF + tx * 4) = o;
        }
        float ps = acc[i][0] * as4.x + acc[i][1] * as4.y + acc[i][2] * as4.z + acc[i][3] * as4.w;
        float pd = acc[i][0] * ad4.x + acc[i][1] * ad4.y + acc[i][2] * ad4.z + acc[i][3] * ad4.w;
#pragma unroll
        for (int o = 8; o; o >>= 1) {
            ps += __shfl_xor_sync(0xffffffffu, ps, o);
            pd += __shfl_xor_sync(0xffffffffu, pd, o);
        }
        if (tx == 0 && row < NN) {
            g_esrc[row] = ps;
            g_ed[row] = pd;
            atomicMax(&bmax, fkey(pd));
        }
    }
    __syncthreads();
    if (tid == 0) atomicMax(&g_Emax, bmax);
}

// ---------------------------------------------------------------------------
// K2: per-j tables + u/v keys + bucket histograms
// ---------------------------------------------------------------------------
__global__ void k_jtab(const float* __restrict__ hub) {
    int i = blockIdx.x * 256 + threadIdx.x;
    if (i >= NN) return;
    float E = funkey(g_Emax);
    float ed = g_ed[i];
    float bp = expf(ed - E);
    float bn = expf(0.2f * (ed - E));
    float2 pb; pb.x = bp; pb.y = bn;
    g_pb2[i] = pb;
    float hT = hub[i] * 0.01f;
    g_hT[i] = hT;
    // slacked candidate keys (superset-safe): py > u  =>  may have py*bp > hT
    float u = fmaxf((hT / bp) * (1.0f - 2e-6f) - 1e-37f, 0.f);
    float v = fmaxf((hT / bn) * (1.0f - 2e-6f) - 1e-37f, 0.f);
    g_u[i] = u;
    float2 vu; vu.x = v; vu.y = u;
    g_vu[i] = vu;
    atomicAdd(&g_histU[buck(u)], 1);
    atomicAdd(&g_histV[buck(v)], 1);
}

// ---------------------------------------------------------------------------
// K3: exclusive prefix over both histograms (single block)
// ---------------------------------------------------------------------------
__global__ void k_pref() {
    __shared__ int sU[1024], sV[1024];
    int t = threadIdx.x;
    int baseI = t * 16;
    int locU[16], locV[16];
    int aU = 0, aV = 0;
#pragma unroll
    for (int q = 0; q < 16; q++) {
        locU[q] = g_histU[baseI + q]; aU += locU[q];
        locV[q] = g_histV[baseI + q]; aV += locV[q];
    }
    sU[t] = aU; sV[t] = aV;
    __syncthreads();
    for (int d = 1; d < 1024; d <<= 1) {
        int xU = (t >= d) ? sU[t - d] : 0;
        int xV = (t >= d) ? sV[t - d] : 0;
        __syncthreads();
        sU[t] += xU; sV[t] += xV;
        __syncthreads();
    }
    int exU = sU[t] - aU, exV = sV[t] - aV;
#pragma unroll
    for (int q = 0; q < 16; q++) {
        g_offU[baseI + q] = exU; g_curU[baseI + q] = exU; exU += locU[q];
        g_offV[baseI + q] = exV; g_curV[baseI + q] = exV; exV += locV[q];
    }
    if (t == 1023) { g_offU[NBUCK] = exU; g_offV[NBUCK] = exV; }
}

// ---------------------------------------------------------------------------
// K4: scatter into bucket-sorted arrays
// ---------------------------------------------------------------------------
__global__ void k_scatter() {
    int i = blockIdx.x * 256 + threadIdx.x;
    if (i >= NN) return;
    float u = g_u[i];
    int p1 = atomicAdd(&g_curU[buck(u)], 1);
    g_sortU[p1] = u; g_idxU[p1] = i;
    float2 vu = g_vu[i];
    int p2 = atomicAdd(&g_curV[buck(vu.x)], 1);
    g_sortV[p2] = vu; g_idxV[p2] = i;
}

// ---------------------------------------------------------------------------
// K5: FUSED adj stream: nibble mask + softmax denominator + row params
// ---------------------------------------------------------------------------
__global__ void __launch_bounds__(256) k_scan(const int* __restrict__ adj) {
    __shared__ float srho[8];
    __shared__ float sred[8][8];
    int t = threadIdx.x, warp = t >> 5;
    int b = blockIdx.x;
    int r0 = b * 8;
    if (t < 8) {
        float es = g_esrc[r0 + t];
        float E = funkey(g_Emax);
        srho[t] = expf(-0.8f * (es + E));
    }
    __syncthreads();
    float rho[8], S[8];
#pragma unroll
    for (int r = 0; r < 8; r++) { rho[r] = srho[r]; S[r] = 0.f; }

    const int4* adj4 = reinterpret_cast<const int4*>(adj);
    const float4* pb4 = reinterpret_cast<const float4*>(g_pb2);
    unsigned* nr0 = g_nib4 + (size_t)(b * 2) * NV;
    unsigned* nr1 = g_nib4 + (size_t)(b * 2 + 1) * NV;

    for (int v = t; v < NV; v += 256) {
        int4 a[8];
#pragma unroll
        for (int r = 0; r < 8; r++)
            a[r] = __ldcs(&adj4[(size_t)(r0 + r) * NV + v]);
        float4 p01 = pb4[2 * v];
        float4 p23 = pb4[2 * v + 1];
        unsigned pk0 = 0, pk1 = 0;
#pragma unroll
        for (int r = 0; r < 8; r++) {
            float rr = rho[r];
            float t0 = fmaxf(p01.x, rr * p01.y);
            float t1 = fmaxf(p01.z, rr * p01.w);
            float t2 = fmaxf(p23.x, rr * p23.y);
            float t3 = fmaxf(p23.z, rr * p23.w);
            if (a[r].x > 0) S[r] += t0;
            if (a[r].y > 0) S[r] += t1;
            if (a[r].z > 0) S[r] += t2;
            if (a[r].w > 0) S[r] += t3;
            unsigned nib = (unsigned)(a[r].x | (a[r].y << 1) | (a[r].z << 2) | (a[r].w << 3));
            if (r < 4) pk0 |= nib << (8 * r);
            else       pk1 |= nib << (8 * (r - 4));
        }
        nr0[v] = pk0;
        nr1[v] = pk1;
    }
#pragma unroll
    for (int r = 0; r < 8; r++) {
        float s = S[r];
#pragma unroll
        for (int o = 16; o; o >>= 1) s += __shfl_xor_sync(0xffffffffu, s, o);
        if ((t & 31) == 0) sred[r][warp] = s;
    }
    __syncthreads();
    if (t < 8) {
        float s = sred[t][0];
#pragma unroll
        for (int w = 1; w < 8; w++) s += sred[t][w];
        float inv = 1.0f / s;
        float2 rw; rw.x = inv; rw.y = srho[t] * inv;
        g_rw[r0 + t] = rw;
    }
}

// ---------------------------------------------------------------------------
// K6: sorted-prefix prune + sparse SpMM + ELU. Warp per row (1250 x 8 warps).
// Candidates: prefix of u-sorted list (py > u_j), plus prefix of v-sorted
// list (pz > v_j) deduped by !(u_j < py). Adjacency via nibble-mask bit.
// ---------------------------------------------------------------------------
__global__ void __launch_bounds__(256) k_pruneout(float* __restrict__ out) {
    int t = threadIdx.x;
    int lane = t & 31, w = t >> 5;
    int row = blockIdx.x * 8 + w;
    float2 rw = g_rw[row];
    float py = rw.x, pz = rw.y;
    const unsigned* nib = g_nib4 + (size_t)(row >> 2) * NV;
    int shift = (row & 3) * 8;
    size_t base = (size_t)row * SMAX;
    int cnt = 0;

    // ---- U-prefix candidates ----
    int stopU = g_offU[buck(py) + 1];
    for (int k0 = 0; k0 < stopU; k0 += 32) {
        int k = k0 + lane;
        float uu = g_sortU[k];
        bool cand = (k < stopU) && (uu < py);
        int j = 0; bool sv = false;
        if (cand) {
            j = g_idxU[k];
            sv = (nib[j >> 2] >> (shift + (j & 3))) & 1u;
        }
        unsigned sb = __ballot_sync(0xffffffffu, sv);
        if (sv) g_sj[base + cnt + __popc(sb & ((1u << lane) - 1u))] = j;
        cnt += __popc(sb);
    }
    // ---- V-prefix candidates (dedupe vs U) ----
    int stopV = g_offV[buck(pz) + 1];
    for (int k0 = 0; k0 < stopV; k0 += 32) {
        int k = k0 + lane;
        float2 vu = g_sortV[k];
        bool cand = (k < stopV) && (vu.x < pz) && !(vu.y < py);
        int j = 0; bool sv = false;
        if (cand) {
            j = g_idxV[k];
            sv = (nib[j >> 2] >> (shift + (j & 3))) & 1u;
        }
        unsigned sb = __ballot_sync(0xffffffffu, sv);
        if (sv) g_sj[base + cnt + __popc(sb & ((1u << lane) - 1u))] = j;
        cnt += __popc(sb);
    }

    // ---- SpMM: warp covers all 64 cols (float2 per lane) ----
    int n = cnt;
    const int* sj = g_sj + base;
    const float2* whb = reinterpret_cast<const float2*>(g_Wh);
    float ax = 0.f, ay = 0.f, bx = 0.f, by = 0.f;
    int p = 0;
    for (; p + 1 < n; p += 2) {
        int j0 = sj[p], j1 = sj[p + 1];
        float2 t0 = g_pb2[j0], t1 = g_pb2[j1];
        float h0 = g_hT[j0], h1 = g_hT[j1];
        float2 a0 = whb[(size_t)j0 * 32 + lane];
        float2 a1 = whb[(size_t)j1 * 32 + lane];
        float w0 = fmaxf(fmaxf(py * t0.x, pz * t0.y) - h0, 0.f);
        float w1 = fmaxf(fmaxf(py * t1.x, pz * t1.y) - h1, 0.f);
        ax = fmaf(w0, a0.x, ax); ay = fmaf(w0, a0.y, ay);
        bx = fmaf(w1, a1.x, bx); by = fmaf(w1, a1.y, by);
    }
    if (p < n) {
        int j0 = sj[p];
        float2 t0 = g_pb2[j0];
        float h0 = g_hT[j0];
        float2 a0 = whb[(size_t)j0 * 32 + lane];
        float w0 = fmaxf(fmaxf(py * t0.x, pz * t0.y) - h0, 0.f);
        ax = fmaf(w0, a0.x, ax); ay = fmaf(w0, a0.y, ay);
    }
    ax += bx; ay += by;
    float2 o;
    o.x = ax > 0.f ? ax : expm1f(ax);
    o.y = ay > 0.f ? ay : expm1f(ay);
    reinterpret_cast<float2*>(out)[(size_t)row * 32 + lane] = o;
}

// ---------------------------------------------------------------------------
extern "C" void kernel_launch(void* const* d_in, const int* in_sizes, int n_in,
                              void* d_out, int out_size) {
    const float* h = nullptr; const float* W = nullptr;
    const float* a_src = nullptr; const float* a_dst = nullptr;
    const float* hub = nullptr; const int* adj = nullptr;
    int a_count = 0;
    for (int i = 0; i < n_in; i++) {
        int s = in_sizes[i];
        if (s == NN * 512)        h = (const float*)d_in[i];
        else if (s == 512 * OUTF) W = (const float*)d_in[i];
        else if (s == OUTF) { if (a_count++ == 0) a_src = (const float*)d_in[i];
                              else                a_dst = (const float*)d_in[i]; }
        else if (s == NN)         hub = (const float*)d_in[i];
        else if (s == NN * NN)    adj = (const int*)d_in[i];
    }

    void* emax_ptr = nullptr;
    cudaGetSymbolAddress(&emax_ptr, g_Emax);
    cudaMemsetAsync(emax_ptr, 0x80, sizeof(int));

    k_pad<<<64, 256>>>();
    k_gemm<<<157, 256>>>(h, W, a_src, a_dst);
    k_jtab<<<(NN + 255) / 256, 256>>>(hub);
    k_pref<<<1, 1024>>>();
    k_scatter<<<(NN + 255) / 256, 256>>>();
    k_scan<<<1250, 256>>>(adj);
    k_pruneout<<<1250, 256>>>((float*)d_out);
}

// round 8
// speedup vs baseline: 1.2038x; 1.2038x over previous
#include <cuda_runtime.h>
#include <math.h>

#define NN 10000
#define NV 2500            // NN/4
#define OUTF 64
#define SMAX 10016
#define NSORT 10048        // padded sorted-list length
#define NBUCK 4096

// ---- static scratch ----
__device__ float    g_Wh[NN * OUTF];
__device__ float    g_esrc[NN];
__device__ float    g_ed[NN];
__device__ int      g_Emax;
__device__ float2   g_pb2[NN];        // {bp=exp(ed-E), bn=exp(0.2(ed-E))}
__device__ float    g_hT[NN];         // hub*0.01
__device__ unsigned g_nib4[(size_t)(NN / 4) * NV];
__device__ float2   g_rw[NN];         // {py=1/S', pz=rho/S'}
__device__ int      g_sj[(size_t)NN * SMAX];
// sort machinery
__device__ float    g_u[NN];
__device__ float2   g_vu[NN];
__device__ int      g_histU[NBUCK], g_histV[NBUCK];
__device__ int      g_offU[NBUCK + 1], g_offV[NBUCK + 1];
__device__ int      g_curU[NBUCK], g_curV[NBUCK];
__device__ float    g_sortU[NSORT];
__device__ int      g_idxU[NSORT];
__device__ float2   g_sortV[NSORT];
__device__ int      g_idxV[NSORT];

__device__ __forceinline__ int fkey(float x) {
    int ix = __float_as_int(x);
    return ix >= 0 ? ix : (ix ^ 0x7fffffff);
}
__device__ __forceinline__ float funkey(int k) {
    return __int_as_float(k >= 0 ? k : (k ^ 0x7fffffff));
}
__device__ __forceinline__ unsigned buck(float x) {   // x >= 0 (or NaN/inf)
    unsigned b = __float_as_uint(x) >> 19;
    return b > (NBUCK - 1u) ? (NBUCK - 1u) : b;
}

// ---------------------------------------------------------------------------
// K0: zero histograms + pad sorted arrays
// ---------------------------------------------------------------------------
__global__ void k_pad() {
    int i = blockIdx.x * 256 + threadIdx.x;
    if (i < NBUCK) { g_histU[i] = 0; g_histV[i] = 0; }
    if (i >= NN && i < NSORT) {
        float inf = __int_as_float(0x7F800000);
        g_sortU[i] = inf;
        float2 f; f.x = inf; f.y = inf;
        g_sortV[i] = f;
        g_idxU[i] = 0; g_idxV[i] = 0;
    }
}

// ---------------------------------------------------------------------------
// K1: Wh = h @ W (64x64 tile) + fused edge dots + Emax
// ---------------------------------------------------------------------------
__global__ void k_gemm(const float* __restrict__ h, const float* __restrict__ W,
                       const float* __restrict__ a_src, const float* __restrict__ a_dst) {
    __shared__ float h_s[64][33];
    __shared__ float W_s[32][64];
    __shared__ int bmax;
    int tid = threadIdx.x;
    if (tid == 0) bmax = 0x80000000;
    int tx = tid & 15, ty = tid >> 4;
    int gr0 = blockIdx.x * 64;
    float acc[4][4];
#pragma unroll
    for (int i = 0; i < 4; i++)
#pragma unroll
        for (int j = 0; j < 4; j++) acc[i][j] = 0.f;

    for (int k0 = 0; k0 < 512; k0 += 32) {
        __syncthreads();
#pragma unroll
        for (int it = 0; it < 2; it++) {
            int idx = it * 256 + tid;
            int row = idx >> 3, q = idx & 7;
            float4 h4 = make_float4(0.f, 0.f, 0.f, 0.f);
            if (gr0 + row < NN)
                h4 = *reinterpret_cast<const float4*>(h + (size_t)(gr0 + row) * 512 + k0 + q * 4);
            h_s[row][q * 4 + 0] = h4.x; h_s[row][q * 4 + 1] = h4.y;
            h_s[row][q * 4 + 2] = h4.z; h_s[row][q * 4 + 3] = h4.w;
        }
#pragma unroll
        for (int it = 0; it < 2; it++) {
            int idx = it * 256 + tid;
            int kk = idx >> 4, c4 = (idx & 15) * 4;
            float4 w4 = *reinterpret_cast<const float4*>(W + (size_t)(k0 + kk) * OUTF + c4);
            *reinterpret_cast<float4*>(&W_s[kk][c4]) = w4;
        }
        __syncthreads();
#pragma unroll
        for (int kk = 0; kk < 32; kk++) {
            float4 wv = *reinterpret_cast<const float4*>(&W_s[kk][tx * 4]);
            float hv0 = h_s[ty * 4 + 0][kk];
            float hv1 = h_s[ty * 4 + 1][kk];
            float hv2 = h_s[ty * 4 + 2][kk];
            float hv3 = h_s[ty * 4 + 3][kk];
            acc[0][0] = fmaf(hv0, wv.x, acc[0][0]); acc[0][1] = fmaf(hv0, wv.y, acc[0][1]);
            acc[0][2] = fmaf(hv0, wv.z, acc[0][2]); acc[0][3] = fmaf(hv0, wv.w, acc[0][3]);
            acc[1][0] = fmaf(hv1, wv.x, acc[1][0]); acc[1][1] = fmaf(hv1, wv.y, acc[1][1]);
            acc[1][2] = fmaf(hv1, wv.z, acc[1][2]); acc[1][3] = fmaf(hv1, wv.w, acc[1][3]);
            acc[2][0] = fmaf(hv2, wv.x, acc[2][0]); acc[2][1] = fmaf(hv2, wv.y, acc[2][1]);
            acc[2][2] = fmaf(hv2, wv.z, acc[2][2]); acc[2][3] = fmaf(hv2, wv.w, acc[2][3]);
            acc[3][0] = fmaf(hv3, wv.x, acc[3][0]); acc[3][1] = fmaf(hv3, wv.y, acc[3][1]);
            acc[3][2] = fmaf(hv3, wv.z, acc[3][2]); acc[3][3] = fmaf(hv3, wv.w, acc[3][3]);
        }
    }
    float4 as4 = *reinterpret_cast<const float4*>(a_src + tx * 4);
    float4 ad4 = *reinterpret_cast<const float4*>(a_dst + tx * 4);
#pragma unroll
    for (int i = 0; i < 4; i++) {
        int row = gr0 + ty * 4 + i;
        if (row < NN) {
            float4 o; o.x = acc[i][0]; o.y = acc[i][1]; o.z = acc[i][2]; o.w = acc[i][3];
            *reinterpret_cast<float4*>(g_Wh + (size_t)row * OUTF + tx * 4) = o;
        }
        float ps = acc[i][0] * as4.x + acc[i][1] * as4.y + acc[i][2] * as4.z + acc[i][3] * as4.w;
        float pd = acc[i][0] * ad4.x + acc[i][1] * ad4.y + acc[i][2] * ad4.z + acc[i][3] * ad4.w;
#pragma unroll
        for (int o = 8; o; o >>= 1) {
            ps += __shfl_xor_sync(0xffffffffu, ps, o);
            pd += __shfl_xor_sync(0xffffffffu, pd, o);
        }
        if (tx == 0 && row < NN) {
            g_esrc[row] = ps;
            g_ed[row] = pd;
            atomicMax(&bmax, fkey(pd));
        }
    }
    __syncthreads();
    if (tid == 0) atomicMax(&g_Emax, bmax);
}

// ---------------------------------------------------------------------------
// K2: per-j tables + u/v keys + bucket histograms
// ---------------------------------------------------------------------------
__global__ void k_jtab(const float* __restrict__ hub) {
    int i = blockIdx.x * 256 + threadIdx.x;
    if (i >= NN) return;
    float E = funkey(g_Emax);
    float ed = g_ed[i];
    float bp = expf(ed - E);
    float bn = expf(0.2f * (ed - E));
    float2 pb; pb.x = bp; pb.y = bn;
    g_pb2[i] = pb;
    float hT = hub[i] * 0.01f;
    g_hT[i] = hT;
    float u = fmaxf((hT / bp) * (1.0f - 2e-6f) - 1e-37f, 0.f);
    float v = fmaxf((hT / bn) * (1.0f - 2e-6f) - 1e-37f, 0.f);
    g_u[i] = u;
    float2 vu; vu.x = v; vu.y = u;
    g_vu[i] = vu;
    atomicAdd(&g_histU[buck(u)], 1);
    atomicAdd(&g_histV[buck(v)], 1);
}

// ---------------------------------------------------------------------------
// K3: exclusive prefix over both histograms — two-level shfl scan, 1024 thr.
// Each thread owns 4 buckets; one __syncthreads round trip total.
// ---------------------------------------------------------------------------
__global__ void k_pref() {
    __shared__ int wU[32], wV[32];
    int t = threadIdx.x;
    int lane = t & 31, warp = t >> 5;
    int b0 = t * 4;
    int lU[4], lV[4];
    int aU = 0, aV = 0;
#pragma unroll
    for (int q = 0; q < 4; q++) {
        lU[q] = g_histU[b0 + q]; aU += lU[q];
        lV[q] = g_histV[b0 + q]; aV += lV[q];
    }
    // warp inclusive scan
    int sU = aU, sV = aV;
#pragma unroll
    for (int d = 1; d < 32; d <<= 1) {
        int xU = __shfl_up_sync(0xffffffffu, sU, d);
        int xV = __shfl_up_sync(0xffffffffu, sV, d);
        if (lane >= d) { sU += xU; sV += xV; }
    }
    if (lane == 31) { wU[warp] = sU; wV[warp] = sV; }
    __syncthreads();
    if (warp == 0) {
        int pU = wU[lane], pV = wV[lane];
#pragma unroll
        for (int d = 1; d < 32; d <<= 1) {
            int xU = __shfl_up_sync(0xffffffffu, pU, d);
            int xV = __shfl_up_sync(0xffffffffu, pV, d);
            if (lane >= d) { pU += xU; pV += xV; }
        }
        wU[lane] = pU; wV[lane] = pV;
    }
    __syncthreads();
    int baseU = (warp ? wU[warp - 1] : 0) + sU - aU;   // exclusive start of this thread's run
    int baseV = (warp ? wV[warp - 1] : 0) + sV - aV;
#pragma unroll
    for (int q = 0; q < 4; q++) {
        g_offU[b0 + q] = baseU; g_curU[b0 + q] = baseU; baseU += lU[q];
        g_offV[b0 + q] = baseV; g_curV[b0 + q] = baseV; baseV += lV[q];
    }
    if (t == 1023) { g_offU[NBUCK] = baseU; g_offV[NBUCK] = baseV; }
}

// ---------------------------------------------------------------------------
// K4: scatter into bucket-sorted arrays
// ---------------------------------------------------------------------------
__global__ void k_scatter() {
    int i = blockIdx.x * 256 + threadIdx.x;
    if (i >= NN) return;
    float u = g_u[i];
    int p1 = atomicAdd(&g_curU[buck(u)], 1);
    g_sortU[p1] = u; g_idxU[p1] = i;
    float2 vu = g_vu[i];
    int p2 = atomicAdd(&g_curV[buck(vu.x)], 1);
    g_sortV[p2] = vu; g_idxV[p2] = i;
}

// ---------------------------------------------------------------------------
// K5: FUSED adj stream: nibble mask + softmax denominator + row params
// ---------------------------------------------------------------------------
__global__ void __launch_bounds__(256) k_scan(const int* __restrict__ adj) {
    __shared__ float srho[8];
    __shared__ float sred[8][8];
    int t = threadIdx.x, warp = t >> 5;
    int b = blockIdx.x;
    int r0 = b * 8;
    if (t < 8) {
        float es = g_esrc[r0 + t];
        float E = funkey(g_Emax);
        srho[t] = expf(-0.8f * (es + E));
    }
    __syncthreads();
    float rho[8], S[8];
#pragma unroll
    for (int r = 0; r < 8; r++) { rho[r] = srho[r]; S[r] = 0.f; }

    const int4* adj4 = reinterpret_cast<const int4*>(adj);
    const float4* pb4 = reinterpret_cast<const float4*>(g_pb2);
    unsigned* nr0 = g_nib4 + (size_t)(b * 2) * NV;
    unsigned* nr1 = g_nib4 + (size_t)(b * 2 + 1) * NV;

    for (int v = t; v < NV; v += 256) {
        int4 a[8];
#pragma unroll
        for (int r = 0; r < 8; r++)
            a[r] = __ldcs(&adj4[(size_t)(r0 + r) * NV + v]);
        float4 p01 = pb4[2 * v];
        float4 p23 = pb4[2 * v + 1];
        unsigned pk0 = 0, pk1 = 0;
#pragma unroll
        for (int r = 0; r < 8; r++) {
            float rr = rho[r];
            float t0 = fmaxf(p01.x, rr * p01.y);
            float t1 = fmaxf(p01.z, rr * p01.w);
            float t2 = fmaxf(p23.x, rr * p23.y);
            float t3 = fmaxf(p23.z, rr * p23.w);
            if (a[r].x > 0) S[r] += t0;
            if (a[r].y > 0) S[r] += t1;
            if (a[r].z > 0) S[r] += t2;
            if (a[r].w > 0) S[r] += t3;
            unsigned nib = (unsigned)(a[r].x | (a[r].y << 1) | (a[r].z << 2) | (a[r].w << 3));
            if (r < 4) pk0 |= nib << (8 * r);
            else       pk1 |= nib << (8 * (r - 4));
        }
        nr0[v] = pk0;
        nr1[v] = pk1;
    }
#pragma unroll
    for (int r = 0; r < 8; r++) {
        float s = S[r];
#pragma unroll
        for (int o = 16; o; o >>= 1) s += __shfl_xor_sync(0xffffffffu, s, o);
        if ((t & 31) == 0) sred[r][warp] = s;
    }
    __syncthreads();
    if (t < 8) {
        float s = sred[t][0];
#pragma unroll
        for (int w = 1; w < 8; w++) s += sred[t][w];
        float inv = 1.0f / s;
        float2 rw; rw.x = inv; rw.y = srho[t] * inv;
        g_rw[r0 + t] = rw;
    }
}

// ---------------------------------------------------------------------------
// K6: sorted-prefix prune + sparse SpMM + ELU. Warp per row (1250 x 8 warps).
// ---------------------------------------------------------------------------
__global__ void __launch_bounds__(256) k_pruneout(float* __restrict__ out) {
    int t = threadIdx.x;
    int lane = t & 31, w = t >> 5;
    int row = blockIdx.x * 8 + w;
    float2 rw = g_rw[row];
    float py = rw.x, pz = rw.y;
    const unsigned* nib = g_nib4 + (size_t)(row >> 2) * NV;
    int shift = (row & 3) * 8;
    size_t base = (size_t)row * SMAX;
    int cnt = 0;

    // ---- U-prefix candidates ----
    int stopU = g_offU[buck(py) + 1];
    for (int k0 = 0; k0 < stopU; k0 += 32) {
        int k = k0 + lane;
        float uu = g_sortU[k];
        bool cand = (k < stopU) && (uu < py);
        int j = 0; bool sv = false;
        if (cand) {
            j = g_idxU[k];
            sv = (nib[j >> 2] >> (shift + (j & 3))) & 1u;
        }
        unsigned sb = __ballot_sync(0xffffffffu, sv);
        if (sv) g_sj[base + cnt + __popc(sb & ((1u << lane) - 1u))] = j;
        cnt += __popc(sb);
    }
    // ---- V-prefix candidates (dedupe vs U) ----
    int stopV = g_offV[buck(pz) + 1];
    for (int k0 = 0; k0 < stopV; k0 += 32) {
        int k = k0 + lane;
        float2 vu = g_sortV[k];
        bool cand = (k < stopV) && (vu.x < pz) && !(vu.y < py);
        int j = 0; bool sv = false;
        if (cand) {
            j = g_idxV[k];
            sv = (nib[j >> 2] >> (shift + (j & 3))) & 1u;
        }
        unsigned sb = __ballot_sync(0xffffffffu, sv);
        if (sv) g_sj[base + cnt + __popc(sb & ((1u << lane) - 1u))] = j;
        cnt += __popc(sb);
    }

    // ---- SpMM: warp covers all 64 cols (float2 per lane) ----
    int n = cnt;
    const int* sj = g_sj + base;
    const float2* whb = reinterpret_cast<const float2*>(g_Wh);
    float ax = 0.f, ay = 0.f, bx = 0.f, by = 0.f;
    int p = 0;
    for (; p + 1 < n; p += 2) {
        int j0 = sj[p], j1 = sj[p + 1];
        float2 t0 = g_pb2[j0], t1 = g_pb2[j1];
        float h0 = g_hT[j0], h1 = g_hT[j1];
        float2 a0 = whb[(size_t)j0 * 32 + lane];
        float2 a1 = whb[(size_t)j1 * 32 + lane];
        float w0 = fmaxf(fmaxf(py * t0.x, pz * t0.y) - h0, 0.f);
        float w1 = fmaxf(fmaxf(py * t1.x, pz * t1.y) - h1, 0.f);
        ax = fmaf(w0, a0.x, ax); ay = fmaf(w0, a0.y, ay);
        bx = fmaf(w1, a1.x, bx); by = fmaf(w1, a1.y, by);
    }
    if (p < n) {
        int j0 = sj[p];
        float2 t0 = g_pb2[j0];
        float h0 = g_hT[j0];
        float2 a0 = whb[(size_t)j0 * 32 + lane];
        float w0 = fmaxf(fmaxf(py * t0.x, pz * t0.y) - h0, 0.f);
        ax = fmaf(w0, a0.x, ax); ay = fmaf(w0, a0.y, ay);
    }
    ax += bx; ay += by;
    float2 o;
    o.x = ax > 0.f ? ax : expm1f(ax);
    o.y = ay > 0.f ? ay : expm1f(ay);
    reinterpret_cast<float2*>(out)[(size_t)row * 32 + lane] = o;
}

// ---------------------------------------------------------------------------
extern "C" void kernel_launch(void* const* d_in, const int* in_sizes, int n_in,
                              void* d_out, int out_size) {
    const float* h = nullptr; const float* W = nullptr;
    const float* a_src = nullptr; const float* a_dst = nullptr;
    const float* hub = nullptr; const int* adj = nullptr;
    int a_count = 0;
    for (int i = 0; i < n_in; i++) {
        int s = in_sizes[i];
        if (s == NN * 512)        h = (const float*)d_in[i];
        else if (s == 512 * OUTF) W = (const float*)d_in[i];
        else if (s == OUTF) { if (a_count++ == 0) a_src = (const float*)d_in[i];
                              else                a_dst = (const float*)d_in[i]; }
        else if (s == NN)         hub = (const float*)d_in[i];
        else if (s == NN * NN)    adj = (const int*)d_in[i];
    }

    void* emax_ptr = nullptr;
    cudaGetSymbolAddress(&emax_ptr, g_Emax);
    cudaMemsetAsync(emax_ptr, 0x80, sizeof(int));

    k_pad<<<64, 256>>>();
    k_gemm<<<157, 256>>>(h, W, a_src, a_dst);
    k_jtab<<<(NN + 255) / 256, 256>>>(hub);
    k_pref<<<1, 1024>>>();
    k_scatter<<<(NN + 255) / 256, 256>>>();
    k_scan<<<1250, 256>>>(adj);
    k_pruneout<<<1250, 256>>>((float*)d_out);
}